// round 17
// baseline (speedup 1.0000x reference)
#include <cuda_runtime.h>
#include <math.h>
#include <stdint.h>

// ---------------------------------------------------------------------------
// CombinedElevationEncoder — both convs on bf16 m16n8k16 mma.sync.
//
// Insight 1: dual-CNN branch only consumed through (4,4) block-mean pool ->
//            fuse conv1+relu+conv2+relu+pool; activations never touch GMEM.
// Insight 2: spiking LSTM emits spike(mem-1), mem = sig(o)*tanh(syn) <= 1
//            -> all spikes exactly 0 -> sconv_res == b_proj; scan skipped.
// R16 (resubmit; prior round died on infra before compile): 32x96 tile —
//     wave-quantization fix: 2048 blocks / 296 slots = 6.92 waves (tail
//     ~1.2%) vs 1536/296 = 5.19 (tail ~15.6%). Inner scheduling identical
//     to R15 (conv1 rolling-window quads, conv2 2-row streaming).
//     smem 83.9KB, occ 2. Head = R13 8-way k-split (11.3us measured).
// ---------------------------------------------------------------------------

#define BATCH 32
#define HH    128
#define WW    1536
#define TH    32
#define TW    96
#define GX    (WW / TW)  // 16
#define GY    (HH / TH)  // 4
#define NCONTRIB 4       // (32/TH)*(384/TW) = 1*4

#define IN_ROWS 38       // 32 out rows + 2 (conv2) + 4 (conv1) halo
#define IN_STR  124      // input tile cols (bf16x2 words); quad-aligned, max idx 121
#define C1_ROWS 34       // conv1 rows needed: out rows -1..+32
#define C1_STR  112      // conv1 plane cols (7 strips of 16)
#define N_STRIPS 7
#define N_QUADS  (N_STRIPS * 8)   // 56 quad units (rows 0..31)

// dynamic smem word offsets
#define OFF_INB 0                          // 38*124 = 4712
#define OFF_C1  4712                       // 34*112*4 = 15232
#define OFF_W1B 19944                      // 320
#define OFF_W2B 20264                      // 576
#define OFF_B1  20840
#define OFF_B2  20848
#define OFF_RED 20856                      // 128
#define SMEM_WORDS 20984
#define SMEM_BYTES (SMEM_WORDS * 4)        // 83936

// partial pooled sums: [b][oc][ph][pw][contrib]
__device__ float g_partial[BATCH * 8 * 4 * 4 * NCONTRIB];

// pack two fp32 -> bf16x2 (lo = first arg)
__device__ __forceinline__ uint32_t bfpack(float lo, float hi) {
    uint32_t d;
    asm("cvt.rn.bf16x2.f32 %0, %1, %2;" : "=r"(d) : "f"(hi), "f"(lo));
    return d;
}

// m16n8k16 bf16 mma, accumulate in place (fp32 accum)
__device__ __forceinline__ void mma_bf16(float& c0, float& c1, float& c2, float& c3,
                                         uint32_t a0, uint32_t a1, uint32_t a2, uint32_t a3,
                                         uint32_t b0, uint32_t b1) {
    asm volatile(
        "mma.sync.aligned.m16n8k16.row.col.f32.bf16.bf16.f32 "
        "{%0,%1,%2,%3}, {%4,%5,%6,%7}, {%8,%9}, {%0,%1,%2,%3};"
        : "+f"(c0), "+f"(c1), "+f"(c2), "+f"(c3)
        : "r"(a0), "r"(a1), "r"(a2), "r"(a3), "r"(b0), "r"(b1));
}

// ---------------------------------------------------------------------------
__global__ __launch_bounds__(512, 2)
void conv_fused_kernel(const float* __restrict__ x,      // [B,2,H,W]
                       const float* __restrict__ w1,     // [8,2,5,7]
                       const float* __restrict__ b1,     // [8]
                       const float* __restrict__ w2,     // [8,8,3,5]
                       const float* __restrict__ b2)     // [8]
{
    extern __shared__ __align__(16) uint32_t dsm[];
    uint32_t* sInB = dsm + OFF_INB;   // [row38][col124] bf16x2 (ic0,ic1)
    uint32_t* sC1  = dsm + OFF_C1;    // [pos=row*112+c][4 words: tig -> oc 2tig,2tig+1]
    uint32_t* sW1B = dsm + OFF_W1B;   // [(kh*8+kw)*8+oc]
    uint32_t* sW2B = dsm + OFF_W2B;   // [((kh*6+kw)*4+tg)*8+oc]
    float* sB1s = (float*)(dsm + OFF_B1);
    float* sB2s = (float*)(dsm + OFF_B2);
    float* sRed = (float*)(dsm + OFF_RED);

    const int tid = threadIdx.x;
    const int wid = tid >> 5;
    const int lid = tid & 31;
    const int g   = lid >> 2;     // fragment group
    const int tig = lid & 3;      // thread in group
    const int bx = blockIdx.x, by = blockIdx.y, b = blockIdx.z;
    const int h0 = by * TH - 3;
    const int w0 = bx * TW - 8;   // 4-aligned tile origin (input word col +3 shift)

    // ---- build weight tables ----
    for (int idx = tid; idx < 320; idx += 512) {
        int oc = idx & 7; int t = idx >> 3;
        int kw = t & 7; int kh = t >> 3;
        float lo = 0.f, hi = 0.f;
        if (kw < 7) {
            lo = w1[((oc * 2 + 0) * 5 + kh) * 7 + kw];
            hi = w1[((oc * 2 + 1) * 5 + kh) * 7 + kw];
        }
        sW1B[idx] = bfpack(lo, hi);
    }
    for (int idx = tid; idx < 576; idx += 512) {
        int oc = idx & 7; int t = idx >> 3;
        int tg = t & 3; t >>= 2;
        int kw = t % 6; int kh = t / 6;
        float lo = 0.f, hi = 0.f;
        if (kw < 5) {
            lo = w2[((oc * 8 + 2 * tg)     * 3 + kh) * 5 + kw];
            hi = w2[((oc * 8 + 2 * tg + 1) * 3 + kh) * 5 + kw];
        }
        sW2B[idx] = bfpack(lo, hi);
    }
    if (tid < 8) { sB1s[tid] = b1[tid]; sB2s[tid] = b2[tid]; }

    // ---- load input tile: aligned float4 quads, ic-interleaved bf16 ----
    {
        const float* p0 = x + (size_t)b * 2 * HH * WW;
        const float* p1 = p0 + HH * WW;
        for (int idx = tid; idx < IN_ROWS * (IN_STR / 4); idx += 512) {
            int cq = idx % (IN_STR / 4), row = idx / (IN_STR / 4);
            int gh = h0 + row;
            int gw = w0 + cq * 4;
            float4 v0 = make_float4(0.f, 0.f, 0.f, 0.f);
            float4 v1 = v0;
            if (gh >= 0 && gh < HH && gw >= 0 && gw + 3 < WW) {
                v0 = *(const float4*)&p0[gh * WW + gw];
                v1 = *(const float4*)&p1[gh * WW + gw];
            }
            uint4 wv;
            wv.x = bfpack(v0.x, v1.x);
            wv.y = bfpack(v0.y, v1.y);
            wv.z = bfpack(v0.z, v1.z);
            wv.w = bfpack(v0.w, v1.w);
            *(uint4*)&sInB[row * IN_STR + cq * 4] = wv;
        }
    }
    __syncthreads();

    // ---- conv1 via mma: 56 rolling-window quad units (rows 0..31/strip) ----
    {
        uint32_t bf[10];
        #pragma unroll
        for (int kh = 0; kh < 5; kh++) {
            bf[kh * 2]     = sW1B[(kh * 8 + tig)     * 8 + g];
            bf[kh * 2 + 1] = sW1B[(kh * 8 + tig + 4) * 8 + g];
        }
        const float bi0 = sB1s[2 * tig], bi1 = sB1s[2 * tig + 1];

        for (int u = wid; u < N_QUADS; u += 16) {
            const int s  = u >> 3;
            const int r0 = (u & 7) * 4;
            const int ci = s * 16 + 3;          // input word base (+3 shift)

            uint32_t f[5][4];
            #pragma unroll
            for (int rr = 0; rr < 5; rr++) {
                const uint32_t* q = &sInB[(r0 + rr) * IN_STR + ci];
                f[rr][0] = q[g + tig];            // m=g,   kw=tig
                f[rr][1] = q[g + 8 + tig];        // m=g+8
                f[rr][2] = q[g + tig + 4];        // kw=tig+4
                f[rr][3] = q[g + 8 + tig + 4];
            }

            #pragma unroll
            for (int cr = 0; cr < 4; cr++) {
                float d0 = bi0, d1 = bi1, d2 = bi0, d3 = bi1;
                #pragma unroll
                for (int kh = 0; kh < 5; kh++) {
                    const int w = (cr + kh) % 5;
                    mma_bf16(d0, d1, d2, d3,
                             f[w][0], f[w][1], f[w][2], f[w][3],
                             bf[kh * 2], bf[kh * 2 + 1]);
                }
                const int pos = (r0 + cr) * C1_STR + s * 16;
                sC1[(pos + g)     * 4 + tig] = bfpack(fmaxf(d0, 0.f), fmaxf(d1, 0.f));
                sC1[(pos + g + 8) * 4 + tig] = bfpack(fmaxf(d2, 0.f), fmaxf(d3, 0.f));
                if (cr < 3) {                     // reload window slot cr <- row r0+5+cr
                    const uint32_t* q = &sInB[(r0 + 5 + cr) * IN_STR + ci];
                    f[cr][0] = q[g + tig];
                    f[cr][1] = q[g + 8 + tig];
                    f[cr][2] = q[g + tig + 4];
                    f[cr][3] = q[g + 8 + tig + 4];
                }
            }
        }
    }
    // ---- conv1 pair units: rows 32,33 of each strip (7 units, warps 9..15) ----
    if (wid >= 9) {
        uint32_t bf[10];
        #pragma unroll
        for (int kh = 0; kh < 5; kh++) {
            bf[kh * 2]     = sW1B[(kh * 8 + tig)     * 8 + g];
            bf[kh * 2 + 1] = sW1B[(kh * 8 + tig + 4) * 8 + g];
        }
        const float bi0 = sB1s[2 * tig], bi1 = sB1s[2 * tig + 1];
        const int s  = wid - 9;
        const int r0 = 32;
        const int ci = s * 16 + 3;

        uint32_t f[6][4];
        #pragma unroll
        for (int rr = 0; rr < 6; rr++) {
            const uint32_t* q = &sInB[(r0 + rr) * IN_STR + ci];
            f[rr][0] = q[g + tig];
            f[rr][1] = q[g + 8 + tig];
            f[rr][2] = q[g + tig + 4];
            f[rr][3] = q[g + 8 + tig + 4];
        }
        #pragma unroll
        for (int cr = 0; cr < 2; cr++) {
            float d0 = bi0, d1 = bi1, d2 = bi0, d3 = bi1;
            #pragma unroll
            for (int kh = 0; kh < 5; kh++)
                mma_bf16(d0, d1, d2, d3,
                         f[cr + kh][0], f[cr + kh][1],
                         f[cr + kh][2], f[cr + kh][3],
                         bf[kh * 2], bf[kh * 2 + 1]);
            const int pos = (r0 + cr) * C1_STR + s * 16;
            sC1[(pos + g)     * 4 + tig] = bfpack(fmaxf(d0, 0.f), fmaxf(d1, 0.f));
            sC1[(pos + g + 8) * 4 + tig] = bfpack(fmaxf(d2, 0.f), fmaxf(d3, 0.f));
        }
    }
    __syncthreads();

    // ---- conv2 via mma + pool: warp = out rows (2wid, 2wid+1); streaming ----
    {
        uint32_t bf[18];
        #pragma unroll
        for (int kh = 0; kh < 3; kh++)
            #pragma unroll
            for (int kw6 = 0; kw6 < 6; kw6++)
                bf[kh * 6 + kw6] = sW2B[((kh * 6 + kw6) * 4 + tig) * 8 + g];
        const float bi0 = sB2s[2 * tig], bi1 = sB2s[2 * tig + 1];
        const int row0 = 2 * wid;           // out rows row0, row0+1

        float s0 = 0.f, s1 = 0.f;
        #pragma unroll
        for (int ch = 0; ch < 6; ch++) {
            const int c0 = ch * 16;
            float a0 = bi0, a1 = bi1, a2 = bi0, a3 = bi1;   // acc row0
            float e0 = bi0, e1 = bi1, e2 = bi0, e3 = bi1;   // acc row0+1
            #pragma unroll
            for (int cr = 0; cr < 4; cr++) {
                const uint32_t* pp = &sC1[((row0 + cr) * C1_STR + c0 + g) * 4];
                uint32_t fl[6], fh[6];
                #pragma unroll
                for (int k = 0; k < 6; k++) {
                    fl[k] = pp[k * 4 + tig];
                    fh[k] = pp[(k + 8) * 4 + tig];
                }
                if (cr <= 2) {       // row0, kh = cr
                    #pragma unroll
                    for (int j = 0; j < 3; j++)
                        mma_bf16(a0, a1, a2, a3,
                                 fl[2 * j], fh[2 * j], fl[2 * j + 1], fh[2 * j + 1],
                                 bf[cr * 6 + 2 * j], bf[cr * 6 + 2 * j + 1]);
                }
                if (cr >= 1) {       // row0+1, kh = cr-1
                    #pragma unroll
                    for (int j = 0; j < 3; j++)
                        mma_bf16(e0, e1, e2, e3,
                                 fl[2 * j], fh[2 * j], fl[2 * j + 1], fh[2 * j + 1],
                                 bf[(cr - 1) * 6 + 2 * j], bf[(cr - 1) * 6 + 2 * j + 1]);
                }
            }
            s0 += fmaxf(a0, 0.f) + fmaxf(a2, 0.f) + fmaxf(e0, 0.f) + fmaxf(e2, 0.f);
            s1 += fmaxf(a1, 0.f) + fmaxf(a3, 0.f) + fmaxf(e1, 0.f) + fmaxf(e3, 0.f);
        }
        // reduce over g (lane bits 2..4); s0 = oc 2tig, s1 = oc 2tig+1
        #pragma unroll
        for (int off = 4; off <= 16; off <<= 1) {
            s0 += __shfl_xor_sync(0xffffffffu, s0, off);
            s1 += __shfl_xor_sync(0xffffffffu, s1, off);
        }
        if (lid < 4) {
            sRed[wid * 8 + 2 * tig]     = s0;
            sRed[wid * 8 + 2 * tig + 1] = s1;
        }
    }
    __syncthreads();

    // deterministic partial write: one fixed slot per block (no atomics)
    if (tid < 8) {
        float t = 0.f;
        #pragma unroll
        for (int wz = 0; wz < 16; wz++) t += sRed[wz * 8 + tid];
        const int ph = by;                          // 1 row-tile per pool cell
        const int pw = bx >> 2, subx = bx & 3;      // 4 col-tiles per pool cell
        g_partial[(((b * 8 + tid) * 4 + ph) * 4 + pw) * NCONTRIB + subx] = t;
    }
}

// ---------------------------------------------------------------------------
// Head: grid (24, 32). seg -> branch (seg>>3) and 64-col segment (seg&7).
// 256 thr = 8 ks x 32 jq; jq owns 2 cols. sconv branch == b_proj.
// ---------------------------------------------------------------------------
__global__ __launch_bounds__(256)
void head_kernel(const float* __restrict__ distance,
                 const float* __restrict__ azimuth,
                 const float* __restrict__ elevation,
                 const float* __restrict__ W_dist, const float* __restrict__ b_dist,
                 const float* __restrict__ W_az,   const float* __restrict__ b_az,
                 const float* __restrict__ W_el,   const float* __restrict__ b_el,
                 const float* __restrict__ W_res,  const float* __restrict__ b_res,
                 const float* __restrict__ b_proj,
                 const float* __restrict__ cnn_gain,
                 const float* __restrict__ sconv_gain,
                 float* __restrict__ out)
{
    __shared__ float sv[256];
    __shared__ float sp[128];
    __shared__ float2 sacc[8][32];
    __shared__ float2 slr[8][32];

    const int tid = threadIdx.x;
    const int jq  = tid & 31;
    const int ks  = tid >> 5;          // 0..7
    const int b   = blockIdx.y;
    const int seg = blockIdx.x;        // 0..23
    const int branch = seg >> 3;       // uniform per block
    const int j = (seg & 7) * 64 + jq * 2;   // col within 512

    const float* vec = (branch == 0) ? distance : (branch == 1) ? azimuth : elevation;
    sv[tid] = vec[b * 256 + tid];

    if (branch == 2 && tid < 128) {
        const float* pp = g_partial + (b * 128 + tid) * NCONTRIB;
        float t = 0.f;
        #pragma unroll
        for (int i = 0; i < NCONTRIB; i++) t += pp[i];
        sp[tid] = t * (1.0f / (32.0f * 384.0f));
    }
    __syncthreads();

    const float* Wm = (branch == 0) ? W_dist : (branch == 1) ? W_az : W_el;
    float2 acc = make_float2(0.f, 0.f);
    #pragma unroll 8
    for (int k = ks * 32; k < ks * 32 + 32; k++) {
        float s = sv[k];
        float2 w = *(const float2*)&Wm[k * 512 + j];
        acc.x = fmaf(s, w.x, acc.x);
        acc.y = fmaf(s, w.y, acc.y);
    }
    sacc[ks][jq] = acc;

    if (branch == 2) {
        float2 lr = make_float2(0.f, 0.f);
        #pragma unroll 8
        for (int k = ks * 16; k < ks * 16 + 16; k++) {
            float s = sp[k];
            float2 w = *(const float2*)&W_res[k * 512 + j];
            lr.x = fmaf(s, w.x, lr.x);
            lr.y = fmaf(s, w.y, lr.y);
        }
        slr[ks][jq] = lr;
    }
    __syncthreads();

    if (ks == 0) {
        float rx = 0.f, ry = 0.f;
        #pragma unroll
        for (int p = 0; p < 8; p++) { rx += sacc[p][jq].x; ry += sacc[p][jq].y; }

        float2 r;
        if (branch == 0) {
            r.x = fmaxf(rx + b_dist[j],     0.f);
            r.y = fmaxf(ry + b_dist[j + 1], 0.f);
        } else if (branch == 1) {
            r.x = fmaxf(rx + b_az[j],     0.f);
            r.y = fmaxf(ry + b_az[j + 1], 0.f);
        } else {
            float bx0 = fmaxf(rx + b_el[j],     0.f);
            float by0 = fmaxf(ry + b_el[j + 1], 0.f);
            float lx = 0.f, ly = 0.f;
            #pragma unroll
            for (int p = 0; p < 8; p++) { lx += slr[p][jq].x; ly += slr[p][jq].y; }
            lx += b_res[j]; ly += b_res[j + 1];
            float cs = 0.5f / (1.0f + expf(-cnn_gain[0]));
            float ss = 0.4f / (1.0f + expf(-sconv_gain[0]));
            r.x = fmaxf(bx0 + cs * lx + ss * b_proj[j],     0.f);
            r.y = fmaxf(by0 + cs * ly + ss * b_proj[j + 1], 0.f);
        }
        *(float2*)&out[b * 1536 + branch * 512 + j] = r;
    }
}

// ---------------------------------------------------------------------------
extern "C" void kernel_launch(void* const* d_in, const int* in_sizes, int n_in,
                              void* d_out, int out_size)
{
    const float* distance   = (const float*)d_in[0];
    const float* azimuth    = (const float*)d_in[1];
    const float* elevation  = (const float*)d_in[2];
    const float* rspikes    = (const float*)d_in[3];
    const float* W_dist     = (const float*)d_in[4];
    const float* b_dist     = (const float*)d_in[5];
    const float* W_az       = (const float*)d_in[6];
    const float* b_az       = (const float*)d_in[7];
    const float* W_el       = (const float*)d_in[8];
    const float* b_el       = (const float*)d_in[9];
    const float* conv1_w    = (const float*)d_in[10];
    const float* conv1_b    = (const float*)d_in[11];
    const float* conv2_w    = (const float*)d_in[12];
    const float* conv2_b    = (const float*)d_in[13];
    const float* W_res      = (const float*)d_in[14];
    const float* b_res      = (const float*)d_in[15];
    const float* b_proj     = (const float*)d_in[19];
    const float* cnn_gain   = (const float*)d_in[20];
    const float* sconv_gain = (const float*)d_in[21];

    cudaFuncSetAttribute(conv_fused_kernel,
                         cudaFuncAttributeMaxDynamicSharedMemorySize, SMEM_BYTES);

    dim3 gconv(GX, GY, BATCH);
    conv_fused_kernel<<<gconv, 512, SMEM_BYTES>>>(rspikes, conv1_w, conv1_b,
                                                  conv2_w, conv2_b);

    dim3 ghead(24, 32);
    head_kernel<<<ghead, 256>>>(distance, azimuth, elevation,
                                W_dist, b_dist, W_az, b_az, W_el, b_el,
                                W_res, b_res, b_proj, cnn_gain, sconv_gain,
                                (float*)d_out);
}